// round 15
// baseline (speedup 1.0000x reference)
#include <cuda_runtime.h>
#include <cuda_fp16.h>
#include <cstdint>
#include <math.h>

// Problem constants (fixed by the reference)
#define BATCH   2
#define SEQ     2048
#define DMODEL  1024
#define NH      16
#define HD      64
#define TOKENS  (BATCH*SEQ)          // 4096
#define NHEADS_TOTAL (BATCH*NH)      // 32

// ---------------------------------------------------------------------------
// Scratch (__device__ globals; allocation in kernel_launch is forbidden)
// ---------------------------------------------------------------------------
__device__ __half g_xs  [(size_t)TOKENS * DMODEL];       // x rounded fp16
__device__ __half g_wq  [(size_t)3 * DMODEL * DMODEL];   // rounded fp16
__device__ __half g_wo  [(size_t)DMODEL * DMODEL];       // rounded fp16
__device__ __half g_hs  [(size_t)TOKENS * DMODEL];       // attention out fp16

// Per-head attention operands, all [head][s][64] natural layout
#define HEADELEMS ((size_t)NHEADS_TOTAL * SEQ * HD)
__device__ __half g_q  [HEADELEMS];
__device__ __half g_k  [HEADELEMS];
__device__ __half g_v  [HEADELEMS];

// ---------------------------------------------------------------------------
// PTX helpers (sm_80-era instructions only — compute_100-safe)
// ---------------------------------------------------------------------------
__device__ __forceinline__ uint32_t smem_u32(const void* p) {
    uint32_t a;
    asm("{ .reg .u64 t; cvta.to.shared.u64 t, %1; cvt.u32.u64 %0, t; }"
        : "=r"(a) : "l"(p));
    return a;
}

#define CP_ASYNC16(dst, src) \
    asm volatile("cp.async.cg.shared.global [%0], [%1], 16;" \
                 :: "r"(dst), "l"(src) : "memory")
#define CP_COMMIT() asm volatile("cp.async.commit_group;" ::: "memory")
#define CP_WAIT(N)  asm volatile("cp.async.wait_group %0;" :: "n"(N) : "memory")

__device__ __forceinline__ void ldsm_x4(uint32_t& r0, uint32_t& r1,
                                        uint32_t& r2, uint32_t& r3, uint32_t addr) {
    asm volatile("ldmatrix.sync.aligned.m8n8.x4.shared.b16 {%0,%1,%2,%3}, [%4];"
                 : "=r"(r0), "=r"(r1), "=r"(r2), "=r"(r3) : "r"(addr));
}

__device__ __forceinline__ void ldsm_x4_t(uint32_t& r0, uint32_t& r1,
                                          uint32_t& r2, uint32_t& r3, uint32_t addr) {
    asm volatile("ldmatrix.sync.aligned.m8n8.x4.trans.shared.b16 {%0,%1,%2,%3}, [%4];"
                 : "=r"(r0), "=r"(r1), "=r"(r2), "=r"(r3) : "r"(addr));
}

__device__ __forceinline__ void mma16816(float* c, uint32_t a0, uint32_t a1,
                                         uint32_t a2, uint32_t a3,
                                         uint32_t b0, uint32_t b1) {
    asm volatile(
        "mma.sync.aligned.m16n8k16.row.col.f32.f16.f16.f32 "
        "{%0,%1,%2,%3}, {%4,%5,%6,%7}, {%8,%9}, {%0,%1,%2,%3};"
        : "+f"(c[0]), "+f"(c[1]), "+f"(c[2]), "+f"(c[3])
        : "r"(a0), "r"(a1), "r"(a2), "r"(a3), "r"(b0), "r"(b1));
}

__device__ __forceinline__ uint32_t pack_half2(float a, float b) {
    __half2 h2 = __floats2half2_rn(a, b);
    return *(uint32_t*)&h2;
}

// ---------------------------------------------------------------------------
// round_all: one launch rounds x, Wqkv, Wo to fp16.
// Block ranges: [0,2048) -> x, [2048,3584) -> Wqkv, [3584,4096) -> Wo.
// ---------------------------------------------------------------------------
__global__ __launch_bounds__(256) void round_all(
    const float* __restrict__ x, const float* __restrict__ wq_f,
    const float* __restrict__ wo_f) {
    int bid = blockIdx.x;
    const float* in;
    __half* out;
    int blk;
    if (bid < 2048)      { in = x;    out = g_xs; blk = bid; }
    else if (bid < 3584) { in = wq_f; out = g_wq; blk = bid - 2048; }
    else                 { in = wo_f; out = g_wo; blk = bid - 3584; }
    int base = (blk * 256 + threadIdx.x) * 8;
    float4 f0 = *(const float4*)(in + base);
    float4 f1 = *(const float4*)(in + base + 4);
    __half2 a = __floats2half2_rn(f0.x, f0.y);
    __half2 b = __floats2half2_rn(f0.z, f0.w);
    __half2 c = __floats2half2_rn(f1.x, f1.y);
    __half2 d = __floats2half2_rn(f1.z, f1.w);
    *(uint4*)(out + base) = make_uint4(*(uint32_t*)&a, *(uint32_t*)&b,
                                       *(uint32_t*)&c, *(uint32_t*)&d);
}

// ---------------------------------------------------------------------------
// fp16 warp-MMA GEMM, grid-stride PERSISTENT over tiles (removes wave
// quantization: 296 CTAs = 2/SM x 148 SM; each loops t += gridDim.x).
// CTA tile 128x128, 8 warps x (64x32), K-chunk 64, 144B padded rows,
// 3-stage cp.async per tile, A-fragment software prefetch.
// MODE 0: plain fp32 C store. MODE 1: fused per-head QKV epilogue.
// ---------------------------------------------------------------------------
#define GROWB 144                       // 64 fp16 (128B) + 16B pad
#define G4_T  (128 * GROWB)             // 18432 per tile (A or B)
#define G4_STAGE (2 * G4_T)             // 36864
#define G4_SMEM (3 * G4_STAGE)          // 110592
#define GTHREADS 256
#define NPERSIST 296                    // 2 CTAs/SM x 148 SMs

__device__ __forceinline__ void g4_issue(
    uint32_t stage, const __half* __restrict__ A, const __half* __restrict__ B,
    int kc, int K, int tid) {
    #pragma unroll
    for (int i = 0; i < 8; ++i) {
        int idx = i * GTHREADS + tid;    // 0..2047
        int mat = idx >> 10;             // 0:A 1:B
        int rem = idx & 1023;
        int row = rem >> 3;
        int c   = rem & 7;
        const __half* src = (mat ? B : A) + (size_t)row * K + kc * 64 + c * 8;
        CP_ASYNC16(stage + mat * G4_T + row * GROWB + c * 16, src);
    }
}

template<int MODE>
__global__ __launch_bounds__(GTHREADS, 2) void gemm_fp16(
    const __half* __restrict__ A, const __half* __restrict__ B,
    float* __restrict__ C, int M, int N, int K) {
    extern __shared__ char smem[];
    const uint32_t sb = smem_u32(smem);

    const int tid = threadIdx.x;
    const int wid = tid >> 5;
    const int lid = tid & 31;
    const int wm  = wid & 1;       // 0..1 -> 64 rows
    const int wn  = wid >> 1;      // 0..3 -> 32 cols

    const uint32_t offA = (((lid >> 3) & 1) * 8 + (lid & 7)) * GROWB + (lid >> 4) * 16;
    const uint32_t offB = ((lid >> 4) * 8 + (lid & 7)) * GROWB + ((lid >> 3) & 1) * 16;

    const int ncols  = N / 128;
    const int ntiles = (M / 128) * ncols;
    const int nch    = K / 64;

    for (int t = blockIdx.x; t < ntiles; t += gridDim.x) {
        const int brow = t / ncols;
        const int bcol = t % ncols;

        const __half* Ab = A + (size_t)brow * 128 * K;
        const __half* Bb = B + (size_t)bcol * 128 * K;

        float acc[4][4][4];
        #pragma unroll
        for (int i = 0; i < 4; ++i)
            #pragma unroll
            for (int j = 0; j < 4; ++j)
                #pragma unroll
                for (int e = 0; e < 4; ++e) acc[i][j][e] = 0.f;

        g4_issue(sb + 0 * G4_STAGE, Ab, Bb, 0, K, tid); CP_COMMIT();
        g4_issue(sb + 1 * G4_STAGE, Ab, Bb, 1, K, tid); CP_COMMIT();

        for (int kc = 0; kc < nch; ++kc) {
            if (kc + 1 < nch) { CP_WAIT(1); } else { CP_WAIT(0); }
            __syncthreads();

            const uint32_t cur = sb + (kc % 3) * G4_STAGE;
            const uint32_t aB  = cur + wm * 64 * GROWB + offA;
            const uint32_t bB  = cur + G4_T + wn * 32 * GROWB + offB;

            #pragma unroll
            for (int k16 = 0; k16 < 4; ++k16) {
                const uint32_t ko = k16 * 32;

                uint32_t bf[8];
                #pragma unroll
                for (int nb = 0; nb < 2; ++nb)
                    ldsm_x4(bf[nb*4], bf[nb*4+1], bf[nb*4+2], bf[nb*4+3],
                            bB + nb * 16 * GROWB + ko);

                // A prefetch: issue ldsm for mt+1 before mt's MMAs
                uint32_t acur[4], anxt[4];
                ldsm_x4(acur[0], acur[1], acur[2], acur[3], aB + ko);
                #pragma unroll
                for (int mt = 0; mt < 4; ++mt) {
                    if (mt < 3)
                        ldsm_x4(anxt[0], anxt[1], anxt[2], anxt[3],
                                aB + (mt + 1) * 16 * GROWB + ko);
                    #pragma unroll
                    for (int nt = 0; nt < 4; ++nt)
                        mma16816(acc[mt][nt], acur[0], acur[1], acur[2], acur[3],
                                 bf[nt * 2], bf[nt * 2 + 1]);
                    #pragma unroll
                    for (int e = 0; e < 4; ++e) acur[e] = anxt[e];
                }
            }

            if (kc + 2 < nch) {
                g4_issue(sb + ((kc + 2) % 3) * G4_STAGE, Ab, Bb, kc + 2, K, tid);
                CP_COMMIT();
            }
        }

        if (MODE == 0) {
            // Plain fp32 epilogue
            const int r0 = brow * 128 + wm * 64 + (lid >> 2);
            const int c0 = bcol * 128 + wn * 32 + (lid & 3) * 2;
            #pragma unroll
            for (int mt = 0; mt < 4; ++mt) {
                #pragma unroll
                for (int nt = 0; nt < 4; ++nt) {
                    float* p = C + (size_t)(r0 + mt * 16) * N + c0 + nt * 8;
                    *(float2*)p                   = make_float2(acc[mt][nt][0], acc[mt][nt][1]);
                    *(float2*)(p + (size_t)8 * N) = make_float2(acc[mt][nt][2], acc[mt][nt][3]);
                }
            }
        } else {
            // Fused QKV epilogue. CTA covers 128 cols = 2 heads; each warp's
            // 32-col block = half a head. Q scaled by 1/8; all single fp16.
            const int section = bcol >> 3;                    // 0=Q 1=K 2=V
            const int head16  = (bcol & 7) * 2 + (wn >> 1);   // 0..15
            const int headg   = (brow >> 4) * NH + head16;
            const int s0      = ((brow * 128) & (SEQ - 1)) + wm * 64 + (lid >> 2);
            const int d0      = (wn & 1) * 32 + (lid & 3) * 2;
            __half* dst = (section == 0) ? g_q : (section == 1) ? g_k : g_v;
            const float scale = (section == 0) ? 0.125f : 1.0f;
            #pragma unroll
            for (int mt = 0; mt < 4; ++mt) {
                #pragma unroll
                for (int nt = 0; nt < 4; ++nt) {
                    int d = d0 + nt * 8;
                    #pragma unroll
                    for (int i = 0; i < 2; ++i) {
                        int s = s0 + mt * 16 + i * 8;
                        size_t idx = ((size_t)headg * SEQ + s) * HD + d;
                        *(__half2*)(dst + idx) = __floats2half2_rn(
                            acc[mt][nt][2*i] * scale, acc[mt][nt][2*i+1] * scale);
                    }
                }
            }
        }
        __syncthreads();   // tile done (smem reuse across loop iterations)
    }
}

// ---------------------------------------------------------------------------
// HMMA flash attention, causal, single-pass fp16. Stages carry two 64-key
// sub-tiles per CP_WAIT/__syncthreads pair; Q fragment prefetched across kc.
// ---------------------------------------------------------------------------
#define AROWB 144
#define SQ_BASE 0
#define SK_BASE 18432
#define SUBT    18432              // one sub-tile: K(9216) + V(9216)
#define KVSTAGE (2 * SUBT)         // 36864: 128 keys
#define ATT_SMEM (SK_BASE + 2 * KVSTAGE)   // 92160
#define NEG_BIG (-1e30f)

// Load one PAIR of 64-key sub-tiles (128 keys of K and V) into kvbase.
__device__ __forceinline__ void att_issue_pair(
    uint32_t kvbase, const __half* __restrict__ Kk,
    const __half* __restrict__ Vv, int jp, int tid) {
    #pragma unroll
    for (int it = 0; it < 8; ++it) {
        int idx = it * 256 + tid;     // 0..2047
        int sub = idx >> 10;          // 0,1
        int rem = idx & 1023;
        int buf = rem >> 9;           // 0:K 1:V
        int r2  = rem & 511;
        int r   = r2 >> 3;
        int c8  = r2 & 7;
        int key = jp * 128 + sub * 64 + r;
        const __half* src = (buf ? Vv : Kk) + (size_t)key * HD + c8 * 8;
        CP_ASYNC16(kvbase + sub * SUBT + buf * 9216 + r * AROWB + c8 * 16, src);
    }
}

__global__ __launch_bounds__(256, 2) void attn_mma() {
    extern __shared__ char smem[];
    const uint32_t sb = smem_u32(smem);

    const int tid = threadIdx.x;
    const int w   = tid >> 5;
    const int lid = tid & 31;
    const int qi  = gridDim.x - 1 - blockIdx.x;   // big tiles first
    const int h   = blockIdx.y;
    const int b   = blockIdx.z;
    const int head = b * NH + h;
    const int qbase = qi * 128;

    const __half* Qq = g_q + ((size_t)head * SEQ + qbase) * HD;
    const __half* Kk = g_k + (size_t)head * SEQ * HD;
    const __half* Vv = g_v + (size_t)head * SEQ * HD;

    // Stage Q: 128 rows x 8 chunks = 1024 cp -> 4/thread
    #pragma unroll
    for (int it = 0; it < 4; ++it) {
        int idx = it * 256 + tid;
        int r   = idx >> 3;
        int c8  = idx & 7;
        CP_ASYNC16(sb + SQ_BASE + r * AROWB + c8 * 16,
                   Qq + (size_t)r * HD + c8 * 8);
    }
    CP_COMMIT();

    const int npairs = qi + 1;         // pairs of 64-key tiles
    att_issue_pair(sb + SK_BASE + 0 * KVSTAGE, Kk, Vv, 0, tid);
    CP_COMMIT();
    att_issue_pair(sb + SK_BASE + 1 * KVSTAGE, Kk, Vv, 1, tid);
    CP_COMMIT();

    const uint32_t offA = (((lid >> 3) & 1) * 8 + (lid & 7)) * AROWB + (lid >> 4) * 16;
    const uint32_t offB = ((lid >> 4) * 8 + (lid & 7)) * AROWB + ((lid >> 3) & 1) * 16;
    const uint32_t qA = sb + SQ_BASE + w * 16 * AROWB + offA;

    float o[8][4];
    #pragma unroll
    for (int nt = 0; nt < 8; ++nt)
        #pragma unroll
        for (int e = 0; e < 4; ++e) o[nt][e] = 0.f;
    float m_i[2] = {NEG_BIG, NEG_BIG};
    float l_i[2] = {0.f, 0.f};

    for (int jp = 0; jp < npairs; ++jp) {
        if (jp < npairs - 1) { CP_WAIT(1); } else { CP_WAIT(0); }
        __syncthreads();

        const uint32_t pairb = sb + SK_BASE + (jp & 1) * KVSTAGE;

        #pragma unroll
        for (int sub = 0; sub < 2; ++sub) {
            const int jt = jp * 2 + sub;          // 64-key tile index
            const uint32_t kvb = pairb + sub * SUBT;

            // ---- S = Q @ K^T (single pass, Q prefetched across kc) ----
            float s[8][4];
            #pragma unroll
            for (int nt = 0; nt < 8; ++nt)
                #pragma unroll
                for (int e = 0; e < 4; ++e) s[nt][e] = 0.f;

            uint32_t qcur[4], qnxt[4];
            ldsm_x4(qcur[0], qcur[1], qcur[2], qcur[3], qA);
            #pragma unroll
            for (int kc = 0; kc < 4; ++kc) {
                const uint32_t ko = kc * 32;
                if (kc < 3)
                    ldsm_x4(qnxt[0], qnxt[1], qnxt[2], qnxt[3], qA + ko + 32);
                #pragma unroll
                for (int p = 0; p < 4; ++p) {
                    uint32_t bk[4];
                    ldsm_x4(bk[0], bk[1], bk[2], bk[3],
                            kvb + p * 16 * AROWB + offB + ko);
                    #pragma unroll
                    for (int half = 0; half < 2; ++half) {
                        int nt = p * 2 + half;
                        mma16816(s[nt], qcur[0], qcur[1], qcur[2], qcur[3],
                                 bk[half * 2], bk[half * 2 + 1]);
                    }
                }
                #pragma unroll
                for (int e = 0; e < 4; ++e) qcur[e] = qnxt[e];
            }

            // ---- causal mask (diagonal tiles only) ----
            if (jt >= 2 * qi) {
                #pragma unroll
                for (int i = 0; i < 2; ++i) {
                    int qg = qbase + w * 16 + (lid >> 2) + i * 8;
                    #pragma unroll
                    for (int nt = 0; nt < 8; ++nt) {
                        int kg = jt * 64 + nt * 8 + (lid & 3) * 2;
                        if (kg > qg)     s[nt][2*i]     = NEG_BIG;
                        if (kg + 1 > qg) s[nt][2*i + 1] = NEG_BIG;
                    }
                }
            }

            // ---- online softmax (quad reductions) ----
            #pragma unroll
            for (int i = 0; i < 2; ++i) {
                float rm = NEG_BIG;
                #pragma unroll
                for (int nt = 0; nt < 8; ++nt)
                    rm = fmaxf(rm, fmaxf(s[nt][2*i], s[nt][2*i+1]));
                rm = fmaxf(rm, __shfl_xor_sync(0xffffffffu, rm, 1));
                rm = fmaxf(rm, __shfl_xor_sync(0xffffffffu, rm, 2));
                float mnew = fmaxf(m_i[i], rm);
                float corr = __expf(m_i[i] - mnew);
                float rs = 0.f;
                #pragma unroll
                for (int nt = 0; nt < 8; ++nt) {
                    float p0 = __expf(s[nt][2*i]     - mnew);
                    float p1 = __expf(s[nt][2*i + 1] - mnew);
                    s[nt][2*i] = p0; s[nt][2*i+1] = p1;
                    rs += p0 + p1;
                }
                rs += __shfl_xor_sync(0xffffffffu, rs, 1);
                rs += __shfl_xor_sync(0xffffffffu, rs, 2);
                l_i[i] = l_i[i] * corr + rs;
                m_i[i] = mnew;
                #pragma unroll
                for (int nt = 0; nt < 8; ++nt) {
                    o[nt][2*i]     *= corr;
                    o[nt][2*i + 1] *= corr;
                }
            }

            // ---- O += P @ V (single pass; V via ldsm.trans) ----
            #pragma unroll
            for (int kc = 0; kc < 4; ++kc) {
                uint32_t ph[4];
                ph[0] = pack_half2(s[2*kc][0],   s[2*kc][1]);
                ph[1] = pack_half2(s[2*kc][2],   s[2*kc][3]);
                ph[2] = pack_half2(s[2*kc+1][0], s[2*kc+1][1]);
                ph[3] = pack_half2(s[2*kc+1][2], s[2*kc+1][3]);

                const uint32_t vrow = kvb + 9216 +
                    (kc * 16 + ((lid >> 3) & 1) * 8 + (lid & 7)) * AROWB +
                    (lid >> 4) * 16;
                #pragma unroll
                for (int p = 0; p < 4; ++p) {
                    uint32_t vf[4];
                    ldsm_x4_t(vf[0], vf[1], vf[2], vf[3], vrow + p * 32);
                    #pragma unroll
                    for (int half = 0; half < 2; ++half) {
                        int nt = p * 2 + half;
                        mma16816(o[nt], ph[0], ph[1], ph[2], ph[3],
                                 vf[half * 2], vf[half * 2 + 1]);
                    }
                }
            }
        }

        __syncthreads();   // all warps done reading buffer (jp&1)
        if (jp + 2 < npairs) {
            att_issue_pair(sb + SK_BASE + (jp & 1) * KVSTAGE, Kk, Vv, jp + 2, tid);
            CP_COMMIT();
        }
    }

    // ---- epilogue: normalize, round to fp16, write hs ----
    #pragma unroll
    for (int i = 0; i < 2; ++i) {
        float inv = 1.f / l_i[i];
        int q = qbase + w * 16 + (lid >> 2) + i * 8;
        size_t rowidx = ((size_t)b * SEQ + q) * DMODEL + h * HD;
        #pragma unroll
        for (int nt = 0; nt < 8; ++nt) {
            int d = nt * 8 + (lid & 3) * 2;
            *(__half2*)(g_hs + rowidx + d) =
                __floats2half2_rn(o[nt][2*i] * inv, o[nt][2*i+1] * inv);
        }
    }
}

// ---------------------------------------------------------------------------
// Launch
// ---------------------------------------------------------------------------
extern "C" void kernel_launch(void* const* d_in, const int* in_sizes, int n_in,
                              void* d_out, int out_size) {
    const float* x    = (const float*)d_in[0];  // [2,2048,1024]
    const float* Wqkv = (const float*)d_in[1];  // [3072,1024]
    const float* Wo   = (const float*)d_in[2];  // [1024,1024]
    float* out = (float*)d_out;                 // [2,2048,1024]

    __half *xs, *wq, *wo, *hs;
    cudaGetSymbolAddress((void**)&xs, g_xs);
    cudaGetSymbolAddress((void**)&wq, g_wq);
    cudaGetSymbolAddress((void**)&wo, g_wo);
    cudaGetSymbolAddress((void**)&hs, g_hs);

    static bool attr_done = false;
    if (!attr_done) {
        cudaFuncSetAttribute(gemm_fp16<1>,
                             cudaFuncAttributeMaxDynamicSharedMemorySize, G4_SMEM);
        cudaFuncSetAttribute(gemm_fp16<0>,
                             cudaFuncAttributeMaxDynamicSharedMemorySize, G4_SMEM);
        cudaFuncSetAttribute(attn_mma,
                             cudaFuncAttributeMaxDynamicSharedMemorySize, ATT_SMEM);
        attr_done = true;
    }

    // Round all operands to fp16 in ONE launch
    round_all<<<4096, 256>>>(x, Wqkv, Wo);

    // 1) QKV projection, persistent grid (768 tiles over 296 CTAs)
    gemm_fp16<1><<<NPERSIST, GTHREADS, G4_SMEM>>>(xs, wq, nullptr,
                                                  TOKENS, 3 * DMODEL, DMODEL);
    // 2) HMMA causal flash attention -> g_hs (fp16)
    {
        dim3 grid(SEQ / 128, NH, BATCH);
        attn_mma<<<grid, 256, ATT_SMEM>>>();
    }
    // 3) Output projection (256 tiles <= 296 CTAs: one tile per CTA)
    gemm_fp16<0><<<NPERSIST, GTHREADS, G4_SMEM>>>(hs, wo, out,
                                                  TOKENS, DMODEL, DMODEL);
}

// round 16
// speedup vs baseline: 1.0185x; 1.0185x over previous
#include <cuda_runtime.h>
#include <cuda_fp16.h>
#include <cstdint>
#include <math.h>

// Problem constants (fixed by the reference)
#define BATCH   2
#define SEQ     2048
#define DMODEL  1024
#define NH      16
#define HD      64
#define TOKENS  (BATCH*SEQ)          // 4096
#define NHEADS_TOTAL (BATCH*NH)      // 32

// ---------------------------------------------------------------------------
// Scratch (__device__ globals; allocation in kernel_launch is forbidden)
// ---------------------------------------------------------------------------
__device__ __half g_xs  [(size_t)TOKENS * DMODEL];       // x rounded fp16
__device__ __half g_wq  [(size_t)3 * DMODEL * DMODEL];   // rounded fp16
__device__ __half g_wo  [(size_t)DMODEL * DMODEL];       // rounded fp16
__device__ __half g_hs  [(size_t)TOKENS * DMODEL];       // attention out fp16

// Per-head attention operands, all [head][s][64] natural layout
#define HEADELEMS ((size_t)NHEADS_TOTAL * SEQ * HD)
__device__ __half g_q  [HEADELEMS];
__device__ __half g_k  [HEADELEMS];
__device__ __half g_v  [HEADELEMS];

// ---------------------------------------------------------------------------
// PTX helpers (sm_80-era instructions only — compute_100-safe)
// ---------------------------------------------------------------------------
__device__ __forceinline__ uint32_t smem_u32(const void* p) {
    uint32_t a;
    asm("{ .reg .u64 t; cvta.to.shared.u64 t, %1; cvt.u32.u64 %0, t; }"
        : "=r"(a) : "l"(p));
    return a;
}

#define CP_ASYNC16(dst, src) \
    asm volatile("cp.async.cg.shared.global [%0], [%1], 16;" \
                 :: "r"(dst), "l"(src) : "memory")
#define CP_COMMIT() asm volatile("cp.async.commit_group;" ::: "memory")
#define CP_WAIT(N)  asm volatile("cp.async.wait_group %0;" :: "n"(N) : "memory")

__device__ __forceinline__ void ldsm_x4(uint32_t& r0, uint32_t& r1,
                                        uint32_t& r2, uint32_t& r3, uint32_t addr) {
    asm volatile("ldmatrix.sync.aligned.m8n8.x4.shared.b16 {%0,%1,%2,%3}, [%4];"
                 : "=r"(r0), "=r"(r1), "=r"(r2), "=r"(r3) : "r"(addr));
}

__device__ __forceinline__ void ldsm_x4_t(uint32_t& r0, uint32_t& r1,
                                          uint32_t& r2, uint32_t& r3, uint32_t addr) {
    asm volatile("ldmatrix.sync.aligned.m8n8.x4.trans.shared.b16 {%0,%1,%2,%3}, [%4];"
                 : "=r"(r0), "=r"(r1), "=r"(r2), "=r"(r3) : "r"(addr));
}

__device__ __forceinline__ void mma16816(float* c, uint32_t a0, uint32_t a1,
                                         uint32_t a2, uint32_t a3,
                                         uint32_t b0, uint32_t b1) {
    asm volatile(
        "mma.sync.aligned.m16n8k16.row.col.f32.f16.f16.f32 "
        "{%0,%1,%2,%3}, {%4,%5,%6,%7}, {%8,%9}, {%0,%1,%2,%3};"
        : "+f"(c[0]), "+f"(c[1]), "+f"(c[2]), "+f"(c[3])
        : "r"(a0), "r"(a1), "r"(a2), "r"(a3), "r"(b0), "r"(b1));
}

__device__ __forceinline__ uint32_t pack_half2(float a, float b) {
    __half2 h2 = __floats2half2_rn(a, b);
    return *(uint32_t*)&h2;
}

// ---------------------------------------------------------------------------
// round_all: one launch rounds x, Wqkv, Wo to fp16.
// Block ranges: [0,2048) -> x, [2048,3584) -> Wqkv, [3584,4096) -> Wo.
// ---------------------------------------------------------------------------
__global__ __launch_bounds__(256) void round_all(
    const float* __restrict__ x, const float* __restrict__ wq_f,
    const float* __restrict__ wo_f) {
    int bid = blockIdx.x;
    const float* in;
    __half* out;
    int blk;
    if (bid < 2048)      { in = x;    out = g_xs; blk = bid; }
    else if (bid < 3584) { in = wq_f; out = g_wq; blk = bid - 2048; }
    else                 { in = wo_f; out = g_wo; blk = bid - 3584; }
    int base = (blk * 256 + threadIdx.x) * 8;
    float4 f0 = *(const float4*)(in + base);
    float4 f1 = *(const float4*)(in + base + 4);
    __half2 a = __floats2half2_rn(f0.x, f0.y);
    __half2 b = __floats2half2_rn(f0.z, f0.w);
    __half2 c = __floats2half2_rn(f1.x, f1.y);
    __half2 d = __floats2half2_rn(f1.z, f1.w);
    *(uint4*)(out + base) = make_uint4(*(uint32_t*)&a, *(uint32_t*)&b,
                                       *(uint32_t*)&c, *(uint32_t*)&d);
}

// ---------------------------------------------------------------------------
// fp16 warp-MMA GEMM: C = A[M,K] @ B[N,K]^T, single-pass fp16 operands.
// CTA tile 128x128, 8 warps x (64x32), K-chunk 64, 144B padded rows,
// 3-stage cp.async, 2 CTAs/SM. A-fragment software prefetch.
// cp.async for chunk kc+2 issued EARLY (right after the barrier) so each
// load gets ~2 chunks of compute to land behind (buffer (kc+2)%3 is free
// at that point: its last reader was chunk kc-1, fenced by this barrier).
// MODE 0: plain fp32 C store. MODE 1: fused per-head QKV epilogue.
// ---------------------------------------------------------------------------
#define GROWB 144                       // 64 fp16 (128B) + 16B pad
#define G4_T  (128 * GROWB)             // 18432 per tile (A or B)
#define G4_STAGE (2 * G4_T)             // 36864
#define G4_SMEM (3 * G4_STAGE)          // 110592
#define GTHREADS 256

__device__ __forceinline__ void g4_issue(
    uint32_t stage, const __half* __restrict__ A, const __half* __restrict__ B,
    int kc, int K, int tid) {
    #pragma unroll
    for (int i = 0; i < 8; ++i) {
        int idx = i * GTHREADS + tid;    // 0..2047
        int mat = idx >> 10;             // 0:A 1:B
        int rem = idx & 1023;
        int row = rem >> 3;
        int c   = rem & 7;
        const __half* src = (mat ? B : A) + (size_t)row * K + kc * 64 + c * 8;
        CP_ASYNC16(stage + mat * G4_T + row * GROWB + c * 16, src);
    }
}

template<int MODE>
__global__ __launch_bounds__(GTHREADS, 2) void gemm_fp16(
    const __half* __restrict__ A, const __half* __restrict__ B,
    float* __restrict__ C, int M, int N, int K) {
    extern __shared__ char smem[];
    const uint32_t sb = smem_u32(smem);

    const int tid = threadIdx.x;
    const int wid = tid >> 5;
    const int lid = tid & 31;
    const int wm  = wid & 1;       // 0..1 -> 64 rows
    const int wn  = wid >> 1;      // 0..3 -> 32 cols

    const int brow = blockIdx.y;
    const int bcol = blockIdx.x;

    const __half* Ab = A + (size_t)brow * 128 * K;
    const __half* Bb = B + (size_t)bcol * 128 * K;

    const uint32_t offA = (((lid >> 3) & 1) * 8 + (lid & 7)) * GROWB + (lid >> 4) * 16;
    const uint32_t offB = ((lid >> 4) * 8 + (lid & 7)) * GROWB + ((lid >> 3) & 1) * 16;

    float acc[4][4][4];
    #pragma unroll
    for (int i = 0; i < 4; ++i)
        #pragma unroll
        for (int j = 0; j < 4; ++j)
            #pragma unroll
            for (int e = 0; e < 4; ++e) acc[i][j][e] = 0.f;

    const int nch = K / 64;      // 16
    g4_issue(sb + 0 * G4_STAGE, Ab, Bb, 0, K, tid); CP_COMMIT();
    g4_issue(sb + 1 * G4_STAGE, Ab, Bb, 1, K, tid); CP_COMMIT();

    for (int kc = 0; kc < nch; ++kc) {
        if (kc + 1 < nch) { CP_WAIT(1); } else { CP_WAIT(0); }
        __syncthreads();

        // Early issue: buffer (kc+2)%3 is free now (last read by kc-1).
        if (kc + 2 < nch) {
            g4_issue(sb + ((kc + 2) % 3) * G4_STAGE, Ab, Bb, kc + 2, K, tid);
            CP_COMMIT();
        }

        const uint32_t cur = sb + (kc % 3) * G4_STAGE;
        const uint32_t aB  = cur + wm * 64 * GROWB + offA;
        const uint32_t bB  = cur + G4_T + wn * 32 * GROWB + offB;

        #pragma unroll
        for (int k16 = 0; k16 < 4; ++k16) {
            const uint32_t ko = k16 * 32;

            uint32_t bf[8];
            #pragma unroll
            for (int nb = 0; nb < 2; ++nb)
                ldsm_x4(bf[nb*4], bf[nb*4+1], bf[nb*4+2], bf[nb*4+3],
                        bB + nb * 16 * GROWB + ko);

            // A prefetch: issue ldsm for mt+1 before mt's MMAs
            uint32_t acur[4], anxt[4];
            ldsm_x4(acur[0], acur[1], acur[2], acur[3], aB + ko);
            #pragma unroll
            for (int mt = 0; mt < 4; ++mt) {
                if (mt < 3)
                    ldsm_x4(anxt[0], anxt[1], anxt[2], anxt[3],
                            aB + (mt + 1) * 16 * GROWB + ko);
                #pragma unroll
                for (int nt = 0; nt < 4; ++nt)
                    mma16816(acc[mt][nt], acur[0], acur[1], acur[2], acur[3],
                             bf[nt * 2], bf[nt * 2 + 1]);
                #pragma unroll
                for (int e = 0; e < 4; ++e) acur[e] = anxt[e];
            }
        }
    }

    if (MODE == 0) {
        // Plain fp32 epilogue
        const int r0 = brow * 128 + wm * 64 + (lid >> 2);
        const int c0 = bcol * 128 + wn * 32 + (lid & 3) * 2;
        #pragma unroll
        for (int mt = 0; mt < 4; ++mt) {
            #pragma unroll
            for (int nt = 0; nt < 4; ++nt) {
                float* p = C + (size_t)(r0 + mt * 16) * N + c0 + nt * 8;
                *(float2*)p                   = make_float2(acc[mt][nt][0], acc[mt][nt][1]);
                *(float2*)(p + (size_t)8 * N) = make_float2(acc[mt][nt][2], acc[mt][nt][3]);
            }
        }
    } else {
        // Fused QKV epilogue. CTA covers 128 cols = 2 heads; each warp's
        // 32-col block = half a head. Q scaled by 1/8; all single fp16.
        const int section = bcol >> 3;                    // 0=Q 1=K 2=V
        const int head16  = (bcol & 7) * 2 + (wn >> 1);   // 0..15
        const int headg   = (brow >> 4) * NH + head16;
        const int s0      = ((brow * 128) & (SEQ - 1)) + wm * 64 + (lid >> 2);
        const int d0      = (wn & 1) * 32 + (lid & 3) * 2;
        __half* dst = (section == 0) ? g_q : (section == 1) ? g_k : g_v;
        const float scale = (section == 0) ? 0.125f : 1.0f;
        #pragma unroll
        for (int mt = 0; mt < 4; ++mt) {
            #pragma unroll
            for (int nt = 0; nt < 4; ++nt) {
                int d = d0 + nt * 8;
                #pragma unroll
                for (int i = 0; i < 2; ++i) {
                    int s = s0 + mt * 16 + i * 8;
                    size_t idx = ((size_t)headg * SEQ + s) * HD + d;
                    *(__half2*)(dst + idx) = __floats2half2_rn(
                        acc[mt][nt][2*i] * scale, acc[mt][nt][2*i+1] * scale);
                }
            }
        }
    }
}

// ---------------------------------------------------------------------------
// HMMA flash attention, causal, single-pass fp16. Stages carry two 64-key
// sub-tiles per CP_WAIT/__syncthreads pair; Q fragment prefetched across kc.
// ---------------------------------------------------------------------------
#define AROWB 144
#define SQ_BASE 0
#define SK_BASE 18432
#define SUBT    18432              // one sub-tile: K(9216) + V(9216)
#define KVSTAGE (2 * SUBT)         // 36864: 128 keys
#define ATT_SMEM (SK_BASE + 2 * KVSTAGE)   // 92160
#define NEG_BIG (-1e30f)

// Load one PAIR of 64-key sub-tiles (128 keys of K and V) into kvbase.
__device__ __forceinline__ void att_issue_pair(
    uint32_t kvbase, const __half* __restrict__ Kk,
    const __half* __restrict__ Vv, int jp, int tid) {
    #pragma unroll
    for (int it = 0; it < 8; ++it) {
        int idx = it * 256 + tid;     // 0..2047
        int sub = idx >> 10;          // 0,1
        int rem = idx & 1023;
        int buf = rem >> 9;           // 0:K 1:V
        int r2  = rem & 511;
        int r   = r2 >> 3;
        int c8  = r2 & 7;
        int key = jp * 128 + sub * 64 + r;
        const __half* src = (buf ? Vv : Kk) + (size_t)key * HD + c8 * 8;
        CP_ASYNC16(kvbase + sub * SUBT + buf * 9216 + r * AROWB + c8 * 16, src);
    }
}

__global__ __launch_bounds__(256, 2) void attn_mma() {
    extern __shared__ char smem[];
    const uint32_t sb = smem_u32(smem);

    const int tid = threadIdx.x;
    const int w   = tid >> 5;
    const int lid = tid & 31;
    const int qi  = gridDim.x - 1 - blockIdx.x;   // big tiles first
    const int h   = blockIdx.y;
    const int b   = blockIdx.z;
    const int head = b * NH + h;
    const int qbase = qi * 128;

    const __half* Qq = g_q + ((size_t)head * SEQ + qbase) * HD;
    const __half* Kk = g_k + (size_t)head * SEQ * HD;
    const __half* Vv = g_v + (size_t)head * SEQ * HD;

    // Stage Q: 128 rows x 8 chunks = 1024 cp -> 4/thread
    #pragma unroll
    for (int it = 0; it < 4; ++it) {
        int idx = it * 256 + tid;
        int r   = idx >> 3;
        int c8  = idx & 7;
        CP_ASYNC16(sb + SQ_BASE + r * AROWB + c8 * 16,
                   Qq + (size_t)r * HD + c8 * 8);
    }
    CP_COMMIT();

    const int npairs = qi + 1;         // pairs of 64-key tiles
    att_issue_pair(sb + SK_BASE + 0 * KVSTAGE, Kk, Vv, 0, tid);
    CP_COMMIT();
    att_issue_pair(sb + SK_BASE + 1 * KVSTAGE, Kk, Vv, 1, tid);
    CP_COMMIT();

    const uint32_t offA = (((lid >> 3) & 1) * 8 + (lid & 7)) * AROWB + (lid >> 4) * 16;
    const uint32_t offB = ((lid >> 4) * 8 + (lid & 7)) * AROWB + ((lid >> 3) & 1) * 16;
    const uint32_t qA = sb + SQ_BASE + w * 16 * AROWB + offA;

    float o[8][4];
    #pragma unroll
    for (int nt = 0; nt < 8; ++nt)
        #pragma unroll
        for (int e = 0; e < 4; ++e) o[nt][e] = 0.f;
    float m_i[2] = {NEG_BIG, NEG_BIG};
    float l_i[2] = {0.f, 0.f};

    for (int jp = 0; jp < npairs; ++jp) {
        if (jp < npairs - 1) { CP_WAIT(1); } else { CP_WAIT(0); }
        __syncthreads();

        const uint32_t pairb = sb + SK_BASE + (jp & 1) * KVSTAGE;

        #pragma unroll
        for (int sub = 0; sub < 2; ++sub) {
            const int jt = jp * 2 + sub;          // 64-key tile index
            const uint32_t kvb = pairb + sub * SUBT;

            // ---- S = Q @ K^T (single pass, Q prefetched across kc) ----
            float s[8][4];
            #pragma unroll
            for (int nt = 0; nt < 8; ++nt)
                #pragma unroll
                for (int e = 0; e < 4; ++e) s[nt][e] = 0.f;

            uint32_t qcur[4], qnxt[4];
            ldsm_x4(qcur[0], qcur[1], qcur[2], qcur[3], qA);
            #pragma unroll
            for (int kc = 0; kc < 4; ++kc) {
                const uint32_t ko = kc * 32;
                if (kc < 3)
                    ldsm_x4(qnxt[0], qnxt[1], qnxt[2], qnxt[3], qA + ko + 32);
                #pragma unroll
                for (int p = 0; p < 4; ++p) {
                    uint32_t bk[4];
                    ldsm_x4(bk[0], bk[1], bk[2], bk[3],
                            kvb + p * 16 * AROWB + offB + ko);
                    #pragma unroll
                    for (int half = 0; half < 2; ++half) {
                        int nt = p * 2 + half;
                        mma16816(s[nt], qcur[0], qcur[1], qcur[2], qcur[3],
                                 bk[half * 2], bk[half * 2 + 1]);
                    }
                }
                #pragma unroll
                for (int e = 0; e < 4; ++e) qcur[e] = qnxt[e];
            }

            // ---- causal mask (diagonal tiles only) ----
            if (jt >= 2 * qi) {
                #pragma unroll
                for (int i = 0; i < 2; ++i) {
                    int qg = qbase + w * 16 + (lid >> 2) + i * 8;
                    #pragma unroll
                    for (int nt = 0; nt < 8; ++nt) {
                        int kg = jt * 64 + nt * 8 + (lid & 3) * 2;
                        if (kg > qg)     s[nt][2*i]     = NEG_BIG;
                        if (kg + 1 > qg) s[nt][2*i + 1] = NEG_BIG;
                    }
                }
            }

            // ---- online softmax (quad reductions) ----
            #pragma unroll
            for (int i = 0; i < 2; ++i) {
                float rm = NEG_BIG;
                #pragma unroll
                for (int nt = 0; nt < 8; ++nt)
                    rm = fmaxf(rm, fmaxf(s[nt][2*i], s[nt][2*i+1]));
                rm = fmaxf(rm, __shfl_xor_sync(0xffffffffu, rm, 1));
                rm = fmaxf(rm, __shfl_xor_sync(0xffffffffu, rm, 2));
                float mnew = fmaxf(m_i[i], rm);
                float corr = __expf(m_i[i] - mnew);
                float rs = 0.f;
                #pragma unroll
                for (int nt = 0; nt < 8; ++nt) {
                    float p0 = __expf(s[nt][2*i]     - mnew);
                    float p1 = __expf(s[nt][2*i + 1] - mnew);
                    s[nt][2*i] = p0; s[nt][2*i+1] = p1;
                    rs += p0 + p1;
                }
                rs += __shfl_xor_sync(0xffffffffu, rs, 1);
                rs += __shfl_xor_sync(0xffffffffu, rs, 2);
                l_i[i] = l_i[i] * corr + rs;
                m_i[i] = mnew;
                #pragma unroll
                for (int nt = 0; nt < 8; ++nt) {
                    o[nt][2*i]     *= corr;
                    o[nt][2*i + 1] *= corr;
                }
            }

            // ---- O += P @ V (single pass; V via ldsm.trans) ----
            #pragma unroll
            for (int kc = 0; kc < 4; ++kc) {
                uint32_t ph[4];
                ph[0] = pack_half2(s[2*kc][0],   s[2*kc][1]);
                ph[1] = pack_half2(s[2*kc][2],   s[2*kc][3]);
                ph[2] = pack_half2(s[2*kc+1][0], s[2*kc+1][1]);
                ph[3] = pack_half2(s[2*kc+1][2], s[2*kc+1][3]);

                const uint32_t vrow = kvb + 9216 +
                    (kc * 16 + ((lid >> 3) & 1) * 8 + (lid & 7)) * AROWB +
                    (lid >> 4) * 16;
                #pragma unroll
                for (int p = 0; p < 4; ++p) {
                    uint32_t vf[4];
                    ldsm_x4_t(vf[0], vf[1], vf[2], vf[3], vrow + p * 32);
                    #pragma unroll
                    for (int half = 0; half < 2; ++half) {
                        int nt = p * 2 + half;
                        mma16816(o[nt], ph[0], ph[1], ph[2], ph[3],
                                 vf[half * 2], vf[half * 2 + 1]);
                    }
                }
            }
        }

        __syncthreads();   // all warps done reading buffer (jp&1)
        if (jp + 2 < npairs) {
            att_issue_pair(sb + SK_BASE + (jp & 1) * KVSTAGE, Kk, Vv, jp + 2, tid);
            CP_COMMIT();
        }
    }

    // ---- epilogue: normalize, round to fp16, write hs ----
    #pragma unroll
    for (int i = 0; i < 2; ++i) {
        float inv = 1.f / l_i[i];
        int q = qbase + w * 16 + (lid >> 2) + i * 8;
        size_t rowidx = ((size_t)b * SEQ + q) * DMODEL + h * HD;
        #pragma unroll
        for (int nt = 0; nt < 8; ++nt) {
            int d = nt * 8 + (lid & 3) * 2;
            *(__half2*)(g_hs + rowidx + d) =
                __floats2half2_rn(o[nt][2*i] * inv, o[nt][2*i+1] * inv);
        }
    }
}

// ---------------------------------------------------------------------------
// Launch
// ---------------------------------------------------------------------------
extern "C" void kernel_launch(void* const* d_in, const int* in_sizes, int n_in,
                              void* d_out, int out_size) {
    const float* x    = (const float*)d_in[0];  // [2,2048,1024]
    const float* Wqkv = (const float*)d_in[1];  // [3072,1024]
    const float* Wo   = (const float*)d_in[2];  // [1024,1024]
    float* out = (float*)d_out;                 // [2,2048,1024]

    __half *xs, *wq, *wo, *hs;
    cudaGetSymbolAddress((void**)&xs, g_xs);
    cudaGetSymbolAddress((void**)&wq, g_wq);
    cudaGetSymbolAddress((void**)&wo, g_wo);
    cudaGetSymbolAddress((void**)&hs, g_hs);

    static bool attr_done = false;
    if (!attr_done) {
        cudaFuncSetAttribute(gemm_fp16<1>,
                             cudaFuncAttributeMaxDynamicSharedMemorySize, G4_SMEM);
        cudaFuncSetAttribute(gemm_fp16<0>,
                             cudaFuncAttributeMaxDynamicSharedMemorySize, G4_SMEM);
        cudaFuncSetAttribute(attn_mma,
                             cudaFuncAttributeMaxDynamicSharedMemorySize, ATT_SMEM);
        attr_done = true;
    }

    // Round all operands to fp16 in ONE launch
    round_all<<<4096, 256>>>(x, Wqkv, Wo);

    // 1) QKV projection with fused per-head epilogue
    {
        dim3 grid(3 * DMODEL / 128, TOKENS / 128);   // (24, 32)
        gemm_fp16<1><<<grid, GTHREADS, G4_SMEM>>>(xs, wq, nullptr,
                                                  TOKENS, 3 * DMODEL, DMODEL);
    }
    // 2) HMMA causal flash attention -> g_hs (fp16)
    {
        dim3 grid(SEQ / 128, NH, BATCH);
        attn_mma<<<grid, 256, ATT_SMEM>>>();
    }
    // 3) Output projection -> out (fp32)
    {
        dim3 grid(DMODEL / 128, TOKENS / 128);       // (8, 32)
        gemm_fp16<0><<<grid, GTHREADS, G4_SMEM>>>(hs, wo, out,
                                                  TOKENS, DMODEL, DMODEL);
    }
}

// round 17
// speedup vs baseline: 1.0456x; 1.0266x over previous
#include <cuda_runtime.h>
#include <cuda_fp16.h>
#include <cstdint>
#include <math.h>

// Problem constants (fixed by the reference)
#define BATCH   2
#define SEQ     2048
#define DMODEL  1024
#define NH      16
#define HD      64
#define TOKENS  (BATCH*SEQ)          // 4096
#define NHEADS_TOTAL (BATCH*NH)      // 32

// ---------------------------------------------------------------------------
// Scratch (__device__ globals; allocation in kernel_launch is forbidden)
// ---------------------------------------------------------------------------
__device__ __half g_xs  [(size_t)TOKENS * DMODEL];       // x rounded fp16
__device__ __half g_wq  [(size_t)3 * DMODEL * DMODEL];   // rounded fp16
__device__ __half g_wo  [(size_t)DMODEL * DMODEL];       // rounded fp16
__device__ __half g_hs  [(size_t)TOKENS * DMODEL];       // attention out fp16

// Per-head attention operands, all [head][s][64] natural layout
#define HEADELEMS ((size_t)NHEADS_TOTAL * SEQ * HD)
__device__ __half g_q  [HEADELEMS];
__device__ __half g_k  [HEADELEMS];
__device__ __half g_v  [HEADELEMS];

// ---------------------------------------------------------------------------
// PTX helpers (sm_80-era instructions only — compute_100-safe)
// ---------------------------------------------------------------------------
__device__ __forceinline__ uint32_t smem_u32(const void* p) {
    uint32_t a;
    asm("{ .reg .u64 t; cvta.to.shared.u64 t, %1; cvt.u32.u64 %0, t; }"
        : "=r"(a) : "l"(p));
    return a;
}

#define CP_ASYNC16(dst, src) \
    asm volatile("cp.async.cg.shared.global [%0], [%1], 16;" \
                 :: "r"(dst), "l"(src) : "memory")
#define CP_COMMIT() asm volatile("cp.async.commit_group;" ::: "memory")
#define CP_WAIT(N)  asm volatile("cp.async.wait_group %0;" :: "n"(N) : "memory")

__device__ __forceinline__ void ldsm_x4(uint32_t& r0, uint32_t& r1,
                                        uint32_t& r2, uint32_t& r3, uint32_t addr) {
    asm volatile("ldmatrix.sync.aligned.m8n8.x4.shared.b16 {%0,%1,%2,%3}, [%4];"
                 : "=r"(r0), "=r"(r1), "=r"(r2), "=r"(r3) : "r"(addr));
}

__device__ __forceinline__ void ldsm_x4_t(uint32_t& r0, uint32_t& r1,
                                          uint32_t& r2, uint32_t& r3, uint32_t addr) {
    asm volatile("ldmatrix.sync.aligned.m8n8.x4.trans.shared.b16 {%0,%1,%2,%3}, [%4];"
                 : "=r"(r0), "=r"(r1), "=r"(r2), "=r"(r3) : "r"(addr));
}

__device__ __forceinline__ void mma16816(float* c, uint32_t a0, uint32_t a1,
                                         uint32_t a2, uint32_t a3,
                                         uint32_t b0, uint32_t b1) {
    asm volatile(
        "mma.sync.aligned.m16n8k16.row.col.f32.f16.f16.f32 "
        "{%0,%1,%2,%3}, {%4,%5,%6,%7}, {%8,%9}, {%0,%1,%2,%3};"
        : "+f"(c[0]), "+f"(c[1]), "+f"(c[2]), "+f"(c[3])
        : "r"(a0), "r"(a1), "r"(a2), "r"(a3), "r"(b0), "r"(b1));
}

__device__ __forceinline__ uint32_t pack_half2(float a, float b) {
    __half2 h2 = __floats2half2_rn(a, b);
    return *(uint32_t*)&h2;
}

// ---------------------------------------------------------------------------
// round_all: one launch rounds x, Wqkv, Wo to fp16.
// Block ranges: [0,2048) -> x, [2048,3584) -> Wqkv, [3584,4096) -> Wo.
// ---------------------------------------------------------------------------
__global__ __launch_bounds__(256) void round_all(
    const float* __restrict__ x, const float* __restrict__ wq_f,
    const float* __restrict__ wo_f) {
    int bid = blockIdx.x;
    const float* in;
    __half* out;
    int blk;
    if (bid < 2048)      { in = x;    out = g_xs; blk = bid; }
    else if (bid < 3584) { in = wq_f; out = g_wq; blk = bid - 2048; }
    else                 { in = wo_f; out = g_wo; blk = bid - 3584; }
    int base = (blk * 256 + threadIdx.x) * 8;
    float4 f0 = *(const float4*)(in + base);
    float4 f1 = *(const float4*)(in + base + 4);
    __half2 a = __floats2half2_rn(f0.x, f0.y);
    __half2 b = __floats2half2_rn(f0.z, f0.w);
    __half2 c = __floats2half2_rn(f1.x, f1.y);
    __half2 d = __floats2half2_rn(f1.z, f1.w);
    *(uint4*)(out + base) = make_uint4(*(uint32_t*)&a, *(uint32_t*)&b,
                                       *(uint32_t*)&c, *(uint32_t*)&d);
}

// ---------------------------------------------------------------------------
// fp16 warp-MMA GEMM: C = A[M,K] @ B[N,K]^T, single-pass fp16 operands.
// CTA tile 128x128, 8 warps x (64x32), K-chunk 64, 144B padded rows,
// 3-stage cp.async, 2 CTAs/SM. A-fragment software prefetch; next-chunk
// cp.async issued after compute (measured best vs early issue / persistent).
// MODE 0: plain fp32 C store. MODE 1: fused per-head QKV epilogue.
// ---------------------------------------------------------------------------
#define GROWB 144                       // 64 fp16 (128B) + 16B pad
#define G4_T  (128 * GROWB)             // 18432 per tile (A or B)
#define G4_STAGE (2 * G4_T)             // 36864
#define G4_SMEM (3 * G4_STAGE)          // 110592
#define GTHREADS 256

__device__ __forceinline__ void g4_issue(
    uint32_t stage, const __half* __restrict__ A, const __half* __restrict__ B,
    int kc, int K, int tid) {
    #pragma unroll
    for (int i = 0; i < 8; ++i) {
        int idx = i * GTHREADS + tid;    // 0..2047
        int mat = idx >> 10;             // 0:A 1:B
        int rem = idx & 1023;
        int row = rem >> 3;
        int c   = rem & 7;
        const __half* src = (mat ? B : A) + (size_t)row * K + kc * 64 + c * 8;
        CP_ASYNC16(stage + mat * G4_T + row * GROWB + c * 16, src);
    }
}

template<int MODE>
__global__ __launch_bounds__(GTHREADS, 2) void gemm_fp16(
    const __half* __restrict__ A, const __half* __restrict__ B,
    float* __restrict__ C, int M, int N, int K) {
    extern __shared__ char smem[];
    const uint32_t sb = smem_u32(smem);

    const int tid = threadIdx.x;
    const int wid = tid >> 5;
    const int lid = tid & 31;
    const int wm  = wid & 1;       // 0..1 -> 64 rows
    const int wn  = wid >> 1;      // 0..3 -> 32 cols

    const int brow = blockIdx.y;
    const int bcol = blockIdx.x;

    const __half* Ab = A + (size_t)brow * 128 * K;
    const __half* Bb = B + (size_t)bcol * 128 * K;

    const uint32_t offA = (((lid >> 3) & 1) * 8 + (lid & 7)) * GROWB + (lid >> 4) * 16;
    const uint32_t offB = ((lid >> 4) * 8 + (lid & 7)) * GROWB + ((lid >> 3) & 1) * 16;

    float acc[4][4][4];
    #pragma unroll
    for (int i = 0; i < 4; ++i)
        #pragma unroll
        for (int j = 0; j < 4; ++j)
            #pragma unroll
            for (int e = 0; e < 4; ++e) acc[i][j][e] = 0.f;

    const int nch = K / 64;      // 16
    g4_issue(sb + 0 * G4_STAGE, Ab, Bb, 0, K, tid); CP_COMMIT();
    g4_issue(sb + 1 * G4_STAGE, Ab, Bb, 1, K, tid); CP_COMMIT();

    for (int kc = 0; kc < nch; ++kc) {
        if (kc + 1 < nch) { CP_WAIT(1); } else { CP_WAIT(0); }
        __syncthreads();

        const uint32_t cur = sb + (kc % 3) * G4_STAGE;
        const uint32_t aB  = cur + wm * 64 * GROWB + offA;
        const uint32_t bB  = cur + G4_T + wn * 32 * GROWB + offB;

        #pragma unroll
        for (int k16 = 0; k16 < 4; ++k16) {
            const uint32_t ko = k16 * 32;

            uint32_t bf[8];
            #pragma unroll
            for (int nb = 0; nb < 2; ++nb)
                ldsm_x4(bf[nb*4], bf[nb*4+1], bf[nb*4+2], bf[nb*4+3],
                        bB + nb * 16 * GROWB + ko);

            // A prefetch: issue ldsm for mt+1 before mt's MMAs
            uint32_t acur[4], anxt[4];
            ldsm_x4(acur[0], acur[1], acur[2], acur[3], aB + ko);
            #pragma unroll
            for (int mt = 0; mt < 4; ++mt) {
                if (mt < 3)
                    ldsm_x4(anxt[0], anxt[1], anxt[2], anxt[3],
                            aB + (mt + 1) * 16 * GROWB + ko);
                #pragma unroll
                for (int nt = 0; nt < 4; ++nt)
                    mma16816(acc[mt][nt], acur[0], acur[1], acur[2], acur[3],
                             bf[nt * 2], bf[nt * 2 + 1]);
                #pragma unroll
                for (int e = 0; e < 4; ++e) acur[e] = anxt[e];
            }
        }

        if (kc + 2 < nch) {
            g4_issue(sb + ((kc + 2) % 3) * G4_STAGE, Ab, Bb, kc + 2, K, tid);
            CP_COMMIT();
        }
    }

    if (MODE == 0) {
        // Plain fp32 epilogue
        const int r0 = brow * 128 + wm * 64 + (lid >> 2);
        const int c0 = bcol * 128 + wn * 32 + (lid & 3) * 2;
        #pragma unroll
        for (int mt = 0; mt < 4; ++mt) {
            #pragma unroll
            for (int nt = 0; nt < 4; ++nt) {
                float* p = C + (size_t)(r0 + mt * 16) * N + c0 + nt * 8;
                *(float2*)p                   = make_float2(acc[mt][nt][0], acc[mt][nt][1]);
                *(float2*)(p + (size_t)8 * N) = make_float2(acc[mt][nt][2], acc[mt][nt][3]);
            }
        }
    } else {
        // Fused QKV epilogue. CTA covers 128 cols = 2 heads; each warp's
        // 32-col block = half a head. Q scaled by 1/8; all single fp16.
        const int section = bcol >> 3;                    // 0=Q 1=K 2=V
        const int head16  = (bcol & 7) * 2 + (wn >> 1);   // 0..15
        const int headg   = (brow >> 4) * NH + head16;
        const int s0      = ((brow * 128) & (SEQ - 1)) + wm * 64 + (lid >> 2);
        const int d0      = (wn & 1) * 32 + (lid & 3) * 2;
        __half* dst = (section == 0) ? g_q : (section == 1) ? g_k : g_v;
        const float scale = (section == 0) ? 0.125f : 1.0f;
        #pragma unroll
        for (int mt = 0; mt < 4; ++mt) {
            #pragma unroll
            for (int nt = 0; nt < 4; ++nt) {
                int d = d0 + nt * 8;
                #pragma unroll
                for (int i = 0; i < 2; ++i) {
                    int s = s0 + mt * 16 + i * 8;
                    size_t idx = ((size_t)headg * SEQ + s) * HD + d;
                    *(__half2*)(dst + idx) = __floats2half2_rn(
                        acc[mt][nt][2*i] * scale, acc[mt][nt][2*i+1] * scale);
                }
            }
        }
    }
}

// ---------------------------------------------------------------------------
// HMMA flash attention, causal, single-pass fp16. Stages carry two 64-key
// sub-tiles per CP_WAIT/__syncthreads pair; Q fragment prefetched across kc.
// ---------------------------------------------------------------------------
#define AROWB 144
#define SQ_BASE 0
#define SK_BASE 18432
#define SUBT    18432              // one sub-tile: K(9216) + V(9216)
#define KVSTAGE (2 * SUBT)         // 36864: 128 keys
#define ATT_SMEM (SK_BASE + 2 * KVSTAGE)   // 92160
#define NEG_BIG (-1e30f)

// Load one PAIR of 64-key sub-tiles (128 keys of K and V) into kvbase.
__device__ __forceinline__ void att_issue_pair(
    uint32_t kvbase, const __half* __restrict__ Kk,
    const __half* __restrict__ Vv, int jp, int tid) {
    #pragma unroll
    for (int it = 0; it < 8; ++it) {
        int idx = it * 256 + tid;     // 0..2047
        int sub = idx >> 10;          // 0,1
        int rem = idx & 1023;
        int buf = rem >> 9;           // 0:K 1:V
        int r2  = rem & 511;
        int r   = r2 >> 3;
        int c8  = r2 & 7;
        int key = jp * 128 + sub * 64 + r;
        const __half* src = (buf ? Vv : Kk) + (size_t)key * HD + c8 * 8;
        CP_ASYNC16(kvbase + sub * SUBT + buf * 9216 + r * AROWB + c8 * 16, src);
    }
}

__global__ __launch_bounds__(256, 2) void attn_mma() {
    extern __shared__ char smem[];
    const uint32_t sb = smem_u32(smem);

    const int tid = threadIdx.x;
    const int w   = tid >> 5;
    const int lid = tid & 31;
    const int qi  = gridDim.x - 1 - blockIdx.x;   // big tiles first
    const int h   = blockIdx.y;
    const int b   = blockIdx.z;
    const int head = b * NH + h;
    const int qbase = qi * 128;

    const __half* Qq = g_q + ((size_t)head * SEQ + qbase) * HD;
    const __half* Kk = g_k + (size_t)head * SEQ * HD;
    const __half* Vv = g_v + (size_t)head * SEQ * HD;

    // Stage Q: 128 rows x 8 chunks = 1024 cp -> 4/thread
    #pragma unroll
    for (int it = 0; it < 4; ++it) {
        int idx = it * 256 + tid;
        int r   = idx >> 3;
        int c8  = idx & 7;
        CP_ASYNC16(sb + SQ_BASE + r * AROWB + c8 * 16,
                   Qq + (size_t)r * HD + c8 * 8);
    }
    CP_COMMIT();

    const int npairs = qi + 1;         // pairs of 64-key tiles
    att_issue_pair(sb + SK_BASE + 0 * KVSTAGE, Kk, Vv, 0, tid);
    CP_COMMIT();
    att_issue_pair(sb + SK_BASE + 1 * KVSTAGE, Kk, Vv, 1, tid);
    CP_COMMIT();

    const uint32_t offA = (((lid >> 3) & 1) * 8 + (lid & 7)) * AROWB + (lid >> 4) * 16;
    const uint32_t offB = ((lid >> 4) * 8 + (lid & 7)) * AROWB + ((lid >> 3) & 1) * 16;
    const uint32_t qA = sb + SQ_BASE + w * 16 * AROWB + offA;

    float o[8][4];
    #pragma unroll
    for (int nt = 0; nt < 8; ++nt)
        #pragma unroll
        for (int e = 0; e < 4; ++e) o[nt][e] = 0.f;
    float m_i[2] = {NEG_BIG, NEG_BIG};
    float l_i[2] = {0.f, 0.f};

    for (int jp = 0; jp < npairs; ++jp) {
        if (jp < npairs - 1) { CP_WAIT(1); } else { CP_WAIT(0); }
        __syncthreads();

        const uint32_t pairb = sb + SK_BASE + (jp & 1) * KVSTAGE;

        #pragma unroll
        for (int sub = 0; sub < 2; ++sub) {
            const int jt = jp * 2 + sub;          // 64-key tile index
            const uint32_t kvb = pairb + sub * SUBT;

            // ---- S = Q @ K^T (single pass, Q prefetched across kc) ----
            float s[8][4];
            #pragma unroll
            for (int nt = 0; nt < 8; ++nt)
                #pragma unroll
                for (int e = 0; e < 4; ++e) s[nt][e] = 0.f;

            uint32_t qcur[4], qnxt[4];
            ldsm_x4(qcur[0], qcur[1], qcur[2], qcur[3], qA);
            #pragma unroll
            for (int kc = 0; kc < 4; ++kc) {
                const uint32_t ko = kc * 32;
                if (kc < 3)
                    ldsm_x4(qnxt[0], qnxt[1], qnxt[2], qnxt[3], qA + ko + 32);
                #pragma unroll
                for (int p = 0; p < 4; ++p) {
                    uint32_t bk[4];
                    ldsm_x4(bk[0], bk[1], bk[2], bk[3],
                            kvb + p * 16 * AROWB + offB + ko);
                    #pragma unroll
                    for (int half = 0; half < 2; ++half) {
                        int nt = p * 2 + half;
                        mma16816(s[nt], qcur[0], qcur[1], qcur[2], qcur[3],
                                 bk[half * 2], bk[half * 2 + 1]);
                    }
                }
                #pragma unroll
                for (int e = 0; e < 4; ++e) qcur[e] = qnxt[e];
            }

            // ---- causal mask (diagonal tiles only) ----
            if (jt >= 2 * qi) {
                #pragma unroll
                for (int i = 0; i < 2; ++i) {
                    int qg = qbase + w * 16 + (lid >> 2) + i * 8;
                    #pragma unroll
                    for (int nt = 0; nt < 8; ++nt) {
                        int kg = jt * 64 + nt * 8 + (lid & 3) * 2;
                        if (kg > qg)     s[nt][2*i]     = NEG_BIG;
                        if (kg + 1 > qg) s[nt][2*i + 1] = NEG_BIG;
                    }
                }
            }

            // ---- online softmax (quad reductions) ----
            #pragma unroll
            for (int i = 0; i < 2; ++i) {
                float rm = NEG_BIG;
                #pragma unroll
                for (int nt = 0; nt < 8; ++nt)
                    rm = fmaxf(rm, fmaxf(s[nt][2*i], s[nt][2*i+1]));
                rm = fmaxf(rm, __shfl_xor_sync(0xffffffffu, rm, 1));
                rm = fmaxf(rm, __shfl_xor_sync(0xffffffffu, rm, 2));
                float mnew = fmaxf(m_i[i], rm);
                float corr = __expf(m_i[i] - mnew);
                float rs = 0.f;
                #pragma unroll
                for (int nt = 0; nt < 8; ++nt) {
                    float p0 = __expf(s[nt][2*i]     - mnew);
                    float p1 = __expf(s[nt][2*i + 1] - mnew);
                    s[nt][2*i] = p0; s[nt][2*i+1] = p1;
                    rs += p0 + p1;
                }
                rs += __shfl_xor_sync(0xffffffffu, rs, 1);
                rs += __shfl_xor_sync(0xffffffffu, rs, 2);
                l_i[i] = l_i[i] * corr + rs;
                m_i[i] = mnew;
                #pragma unroll
                for (int nt = 0; nt < 8; ++nt) {
                    o[nt][2*i]     *= corr;
                    o[nt][2*i + 1] *= corr;
                }
            }

            // ---- O += P @ V (single pass; V via ldsm.trans) ----
            #pragma unroll
            for (int kc = 0; kc < 4; ++kc) {
                uint32_t ph[4];
                ph[0] = pack_half2(s[2*kc][0],   s[2*kc][1]);
                ph[1] = pack_half2(s[2*kc][2],   s[2*kc][3]);
                ph[2] = pack_half2(s[2*kc+1][0], s[2*kc+1][1]);
                ph[3] = pack_half2(s[2*kc+1][2], s[2*kc+1][3]);

                const uint32_t vrow = kvb + 9216 +
                    (kc * 16 + ((lid >> 3) & 1) * 8 + (lid & 7)) * AROWB +
                    (lid >> 4) * 16;
                #pragma unroll
                for (int p = 0; p < 4; ++p) {
                    uint32_t vf[4];
                    ldsm_x4_t(vf[0], vf[1], vf[2], vf[3], vrow + p * 32);
                    #pragma unroll
                    for (int half = 0; half < 2; ++half) {
                        int nt = p * 2 + half;
                        mma16816(o[nt], ph[0], ph[1], ph[2], ph[3],
                                 vf[half * 2], vf[half * 2 + 1]);
                    }
                }
            }
        }

        __syncthreads();   // all warps done reading buffer (jp&1)
        if (jp + 2 < npairs) {
            att_issue_pair(sb + SK_BASE + (jp & 1) * KVSTAGE, Kk, Vv, jp + 2, tid);
            CP_COMMIT();
        }
    }

    // ---- epilogue: normalize, round to fp16, write hs ----
    #pragma unroll
    for (int i = 0; i < 2; ++i) {
        float inv = 1.f / l_i[i];
        int q = qbase + w * 16 + (lid >> 2) + i * 8;
        size_t rowidx = ((size_t)b * SEQ + q) * DMODEL + h * HD;
        #pragma unroll
        for (int nt = 0; nt < 8; ++nt) {
            int d = nt * 8 + (lid & 3) * 2;
            *(__half2*)(g_hs + rowidx + d) =
                __floats2half2_rn(o[nt][2*i] * inv, o[nt][2*i+1] * inv);
        }
    }
}

// ---------------------------------------------------------------------------
// Launch
// ---------------------------------------------------------------------------
extern "C" void kernel_launch(void* const* d_in, const int* in_sizes, int n_in,
                              void* d_out, int out_size) {
    const float* x    = (const float*)d_in[0];  // [2,2048,1024]
    const float* Wqkv = (const float*)d_in[1];  // [3072,1024]
    const float* Wo   = (const float*)d_in[2];  // [1024,1024]
    float* out = (float*)d_out;                 // [2,2048,1024]

    __half *xs, *wq, *wo, *hs;
    cudaGetSymbolAddress((void**)&xs, g_xs);
    cudaGetSymbolAddress((void**)&wq, g_wq);
    cudaGetSymbolAddress((void**)&wo, g_wo);
    cudaGetSymbolAddress((void**)&hs, g_hs);

    static bool attr_done = false;
    if (!attr_done) {
        cudaFuncSetAttribute(gemm_fp16<1>,
                             cudaFuncAttributeMaxDynamicSharedMemorySize, G4_SMEM);
        cudaFuncSetAttribute(gemm_fp16<0>,
                             cudaFuncAttributeMaxDynamicSharedMemorySize, G4_SMEM);
        cudaFuncSetAttribute(attn_mma,
                             cudaFuncAttributeMaxDynamicSharedMemorySize, ATT_SMEM);
        attr_done = true;
    }

    // Round all operands to fp16 in ONE launch
    round_all<<<4096, 256>>>(x, Wqkv, Wo);

    // 1) QKV projection with fused per-head epilogue
    {
        dim3 grid(3 * DMODEL / 128, TOKENS / 128);   // (24, 32)
        gemm_fp16<1><<<grid, GTHREADS, G4_SMEM>>>(xs, wq, nullptr,
                                                  TOKENS, 3 * DMODEL, DMODEL);
    }
    // 2) HMMA causal flash attention -> g_hs (fp16)
    {
        dim3 grid(SEQ / 128, NH, BATCH);
        attn_mma<<<grid, 256, ATT_SMEM>>>();
    }
    // 3) Output projection -> out (fp32)
    {
        dim3 grid(DMODEL / 128, TOKENS / 128);       // (8, 32)
        gemm_fp16<0><<<grid, GTHREADS, G4_SMEM>>>(hs, wo, out,
                                                  TOKENS, DMODEL, DMODEL);
    }
}